// round 2
// baseline (speedup 1.0000x reference)
#include <cuda_runtime.h>
#include <math.h>

#define BS 8
#define LQ 300
#define NQ (BS*LQ)        // 2400
#define DIM 256
#define NH 8
#define NL 4
#define NP 4
#define HD 32
#define LEN_V 34000
#define NPOINT 128        // NH*NL*NP

__constant__ int c_lvlW[4]     = {160, 80, 40, 20};
__constant__ int c_lvlStart[4] = {0, 25600, 32000, 33600};

// Scratch (static device allocations; no runtime alloc allowed)
__device__ float  g_P[NQ * 384];          // [off(256) | attn(128)] per query
__device__ float4 g_smp[NQ * NPOINT];     // (x_pix, y_pix, weight, unused)
__device__ float  g_agg[(size_t)NQ * 2048]; // [q][h][c] aggregated raw value
__device__ float  g_wsum[NQ * NH];
__device__ float  g_Y[NQ * DIM];

// ---------------------------------------------------------------------------
// Generic linear: Out[m, colOff+o] = In[m,:256] @ W[o,:256]^T + bias[o]
// block = 16 rows, blockDim.x = N outputs (<=256), grid = NQ/16
// ---------------------------------------------------------------------------
__global__ void linear_kernel(const float* __restrict__ In,
                              const float* __restrict__ W,
                              const float* __restrict__ bias,
                              float* __restrict__ Out,
                              int ldOut, int colOff) {
    __shared__ float In_s[16][16];
    __shared__ float W_s[16][257];
    const int o = threadIdx.x;
    const int N = blockDim.x;
    const int row0 = blockIdx.x * 16;

    float acc[16];
#pragma unroll
    for (int r = 0; r < 16; ++r) acc[r] = 0.f;

    for (int kc = 0; kc < 256; kc += 16) {
        for (int idx = threadIdx.x; idx < 16 * 16; idx += N) {
            int r = idx >> 4, k = idx & 15;
            In_s[r][k] = In[(row0 + r) * 256 + kc + k];
        }
        for (int idx = threadIdx.x; idx < N * 16; idx += N) {
            int oo = idx >> 4, k = idx & 15;
            W_s[k][oo] = W[oo * 256 + kc + k];
        }
        __syncthreads();
#pragma unroll
        for (int k = 0; k < 16; ++k) {
            float w = W_s[k][o];
#pragma unroll
            for (int r = 0; r < 16; ++r)
                acc[r] += In_s[r][k] * w;
        }
        __syncthreads();
    }
    float b = bias[o];
#pragma unroll
    for (int r = 0; r < 16; ++r)
        Out[(row0 + r) * ldOut + colOff + o] = acc[r] + b;
}

// ---------------------------------------------------------------------------
// Per-query: softmax over 16 (l,p) per head; compute pixel-space sample locs.
// grid = NQ, block = 128 (one thread per (h,l,p) point)
// ---------------------------------------------------------------------------
__global__ void sample_prep_kernel(const float* __restrict__ refpts) {
    const int bq = blockIdx.x;
    const int p = threadIdx.x;          // 0..127
    const int h = p >> 4;
    const int rem = p & 15;             // l*4 + pt
    const int l = rem >> 2;
    const int pt = rem & 3;

    __shared__ float sm_aw[NPOINT];
    float a = g_P[bq * 384 + 256 + h * 16 + rem];
    sm_aw[p] = a;
    __syncthreads();

    float mx = -1e30f;
#pragma unroll
    for (int i = 0; i < 16; ++i) mx = fmaxf(mx, sm_aw[h * 16 + i]);
    float ssum = 0.f;
#pragma unroll
    for (int i = 0; i < 16; ++i) ssum += expf(sm_aw[h * 16 + i] - mx);
    float w = expf(a - mx) / ssum;

    const int Wl = c_lvlW[l];           // H == W per level
    const float fW = (float)Wl;
    float offx = g_P[bq * 384 + (((h * 4 + l) * 4 + pt) * 2) + 0];
    float offy = g_P[bq * 384 + (((h * 4 + l) * 4 + pt) * 2) + 1];
    float rx = refpts[(bq * NL + l) * 2 + 0];
    float ry = refpts[(bq * NL + l) * 2 + 1];
    float locx = rx + offx / fW;
    float locy = ry + offy / fW;

    g_smp[bq * NPOINT + p] = make_float4(locx * fW - 0.5f, locy * fW - 0.5f, w, 0.f);
}

// ---------------------------------------------------------------------------
// The heavy kernel: gather raw 256-d value rows with combined weights.
// grid = NQ, block = 256 (one thread per channel c)
// ---------------------------------------------------------------------------
__global__ void gather_kernel(const float* __restrict__ value) {
    const int bq = blockIdx.x;
    const int b = bq / LQ;
    const int tid = threadIdx.x;        // channel

    __shared__ int   sIdx[NPOINT][4];   // element offsets (pos*256)
    __shared__ float sW[NPOINT][4];
    __shared__ float sWsum[NH];

    if (tid < NH) sWsum[tid] = 0.f;
    __syncthreads();

    if (tid < NPOINT) {
        const int p = tid;
        float4 s = g_smp[bq * NPOINT + p];
        const int l = (p >> 2) & 3;
        const int Wl = c_lvlW[l];
        const int base = c_lvlStart[l];
        const float x = s.x, y = s.y, aw = s.z;
        const float fx = floorf(x), fy = floorf(y);
        const int x0 = (int)fx, y0 = (int)fy;
        const float wx = x - fx, wy = y - fy;
        const float bw[4] = {(1.f - wx) * (1.f - wy), wx * (1.f - wy),
                             (1.f - wx) * wy,         wx * wy};
        const int dx[4] = {0, 1, 0, 1};
        const int dy[4] = {0, 0, 1, 1};
        float tsum = 0.f;
#pragma unroll
        for (int t = 0; t < 4; ++t) {
            int xi = x0 + dx[t], yi = y0 + dy[t];
            bool valid = (xi >= 0) && (xi < Wl) && (yi >= 0) && (yi < Wl);
            float w = valid ? aw * bw[t] : 0.f;
            int xc = min(max(xi, 0), Wl - 1);
            int yc = min(max(yi, 0), Wl - 1);
            sIdx[p][t] = (base + yc * Wl + xc) << 8;   // *256 channels
            sW[p][t] = w;
            tsum += w;
        }
        atomicAdd(&sWsum[p >> 4], tsum);
    }
    __syncthreads();

    const float* vb = value + (size_t)b * ((size_t)LEN_V * DIM) + tid;
    float* aggout = g_agg + (size_t)bq * 2048 + tid;

#pragma unroll
    for (int h = 0; h < NH; ++h) {
        float acc = 0.f;
#pragma unroll 4
        for (int pp = 0; pp < 16; ++pp) {
            const int p = h * 16 + pp;
            acc += sW[p][0] * vb[sIdx[p][0]];
            acc += sW[p][1] * vb[sIdx[p][1]];
            acc += sW[p][2] * vb[sIdx[p][2]];
            acc += sW[p][3] * vb[sIdx[p][3]];
        }
        aggout[h * 256] = acc;
    }
    if (tid < NH) g_wsum[bq * NH + tid] = sWsum[tid];
}

// ---------------------------------------------------------------------------
// Per-head projection: Y[q, o] = agg[q, h(o), :] @ Wv[o,:]^T + wsum[q,h]*bv[o]
// block = 16 rows x 256 outputs, grid = NQ/16
// ---------------------------------------------------------------------------
__global__ void headproj_kernel(const float* __restrict__ Wv,
                                const float* __restrict__ bv) {
    __shared__ float In_s[16][NH][16];
    __shared__ float W_s[16][257];
    const int o = threadIdx.x;          // 0..255
    const int myh = o >> 5;
    const int row0 = blockIdx.x * 16;

    float acc[16];
#pragma unroll
    for (int r = 0; r < 16; ++r) acc[r] = 0.f;

    for (int kc = 0; kc < 256; kc += 16) {
        for (int idx = threadIdx.x; idx < 16 * NH * 16; idx += 256) {
            int r = idx >> 7, h = (idx >> 4) & 7, k = idx & 15;
            In_s[r][h][k] = g_agg[(size_t)(row0 + r) * 2048 + h * 256 + kc + k];
        }
        for (int idx = threadIdx.x; idx < 256 * 16; idx += 256) {
            int oo = idx >> 4, k = idx & 15;
            W_s[k][oo] = Wv[oo * 256 + kc + k];
        }
        __syncthreads();
#pragma unroll
        for (int k = 0; k < 16; ++k) {
            float w = W_s[k][o];
#pragma unroll
            for (int r = 0; r < 16; ++r)
                acc[r] += In_s[r][myh][k] * w;
        }
        __syncthreads();
    }
    float b = bv[o];
#pragma unroll
    for (int r = 0; r < 16; ++r)
        g_Y[(row0 + r) * 256 + o] = acc[r] + g_wsum[(row0 + r) * NH + myh] * b;
}

// ---------------------------------------------------------------------------
extern "C" void kernel_launch(void* const* d_in, const int* in_sizes, int n_in,
                              void* d_out, int out_size) {
    const float* query  = (const float*)d_in[0];
    const float* refpts = (const float*)d_in[1];
    const float* value  = (const float*)d_in[2];
    const float* Wv     = (const float*)d_in[3];
    const float* bv     = (const float*)d_in[4];
    const float* Woff   = (const float*)d_in[5];
    const float* boff   = (const float*)d_in[6];
    const float* Wattn  = (const float*)d_in[7];
    const float* battn  = (const float*)d_in[8];
    const float* Wout   = (const float*)d_in[9];
    const float* bout   = (const float*)d_in[10];
    float* out = (float*)d_out;

    float *pP = nullptr, *pY = nullptr;
    cudaGetSymbolAddress((void**)&pP, g_P);
    cudaGetSymbolAddress((void**)&pY, g_Y);

    // 1+2: sampling offsets + attention logits  (P = query @ [Woff;Wattn]^T + b)
    linear_kernel<<<NQ / 16, 256>>>(query, Woff, boff, pP, 384, 0);
    linear_kernel<<<NQ / 16, 128>>>(query, Wattn, battn, pP, 384, 256);
    // 3: softmax + sampling locations
    sample_prep_kernel<<<NQ, NPOINT>>>(refpts);
    // 4: weighted gather of raw value rows
    gather_kernel<<<NQ, 256>>>(value);
    // 5: per-head value projection applied to aggregates
    headproj_kernel<<<NQ / 16, 256>>>(Wv, bv);
    // 6: output projection
    linear_kernel<<<NQ / 16, 256>>>(pY, Wout, bout, out, 256, 0);
}

// round 3
// speedup vs baseline: 2.8319x; 2.8319x over previous
#include <cuda_runtime.h>
#include <math.h>

#define BS 8
#define LQ 300
#define NQ (BS*LQ)        // 2400
#define DIM 256
#define NH 8
#define NL 4
#define NP 4
#define LEN_V 34000
#define NPOINT 128        // NH*NL*NP

__constant__ int c_lvlW[4]     = {160, 80, 40, 20};
__constant__ int c_lvlStart[4] = {0, 25600, 32000, 33600};

// Scratch
__device__ float g_P[NQ * 384];                    // [off(256) | attn(128)]
__device__ float g_agg[(size_t)NH * NQ * DIM];     // [h][q][c]
__device__ float g_wsum[NQ * NH];
__device__ float g_Y[NQ * DIM];

// ---------------------------------------------------------------------------
// Register-blocked GEMM: C[m, colOff+col0+n] = A[m,:256] @ W[col0+n,:256]^T + bias[col0+n]
// tile 64(M) x 64(N), K-chunk 16, block 256 threads, 4x4 micro-tile per thread.
// ---------------------------------------------------------------------------
__global__ void gemm_kernel(const float* __restrict__ A, int lda,
                            const float* __restrict__ W,
                            const float* __restrict__ bias,
                            float* __restrict__ C, int ldc, int colOff, int M)
{
    __shared__ float As[16][68];
    __shared__ float Bs[16][68];
    const int tid = threadIdx.x;
    const int tx = tid & 15;          // m-quad
    const int ty = tid >> 4;          // n-quad
    const int row0 = blockIdx.x * 64;
    const int col0 = blockIdx.y * 64;
    const int lr = tid >> 2;          // 0..63
    const int kq = (tid & 3) * 4;     // 0,4,8,12

    int arow = row0 + lr; if (arow >= M) arow = M - 1;
    const float* aptr = A + (size_t)arow * lda + kq;
    const float* wptr = W + (size_t)(col0 + lr) * 256 + kq;

    float acc[4][4];
#pragma unroll
    for (int i = 0; i < 4; ++i)
#pragma unroll
        for (int j = 0; j < 4; ++j) acc[i][j] = 0.f;

    for (int kc = 0; kc < 256; kc += 16) {
        float4 va = *(const float4*)(aptr + kc);
        float4 vw = *(const float4*)(wptr + kc);
        As[kq + 0][lr] = va.x; As[kq + 1][lr] = va.y;
        As[kq + 2][lr] = va.z; As[kq + 3][lr] = va.w;
        Bs[kq + 0][lr] = vw.x; Bs[kq + 1][lr] = vw.y;
        Bs[kq + 2][lr] = vw.z; Bs[kq + 3][lr] = vw.w;
        __syncthreads();
#pragma unroll
        for (int k = 0; k < 16; ++k) {
            float4 a4 = ((const float4*)As[k])[tx];
            float4 b4 = ((const float4*)Bs[k])[ty];
            float a[4] = {a4.x, a4.y, a4.z, a4.w};
            float b[4] = {b4.x, b4.y, b4.z, b4.w};
#pragma unroll
            for (int i = 0; i < 4; ++i)
#pragma unroll
                for (int j = 0; j < 4; ++j)
                    acc[i][j] += a[i] * b[j];
        }
        __syncthreads();
    }

    const int gc = col0 + ty * 4;
    float4 bv4 = make_float4(bias[gc], bias[gc + 1], bias[gc + 2], bias[gc + 3]);
#pragma unroll
    for (int i = 0; i < 4; ++i) {
        int r = row0 + tx * 4 + i;
        if (r < M) {
            float4 o = make_float4(acc[i][0] + bv4.x, acc[i][1] + bv4.y,
                                   acc[i][2] + bv4.z, acc[i][3] + bv4.w);
            *(float4*)(&C[(size_t)r * ldc + colOff + gc]) = o;
        }
    }
}

// ---------------------------------------------------------------------------
// Fused prep + gather. One block per query.
//  prologue (threads 0..127): softmax + sampling locs -> packed (w, idx) taps
//  main: slice s = tid>>6 owns heads 2s, 2s+1; 64 channels via float4.
// ---------------------------------------------------------------------------
__global__ void gather_kernel(const float* __restrict__ value,
                              const float* __restrict__ refpts)
{
    __shared__ float2 sPt[NH * 64];   // [h][pp*4+t] = (weight, idx_in_float4_units)
    __shared__ float  sm_aw[NPOINT];
    __shared__ float  sWsum[NH];

    const int bq = blockIdx.x;
    const int b = bq / LQ;
    const int tid = threadIdx.x;

    if (tid < NH) sWsum[tid] = 0.f;
    if (tid < NPOINT) sm_aw[tid] = g_P[bq * 384 + 256 + tid];
    __syncthreads();

    if (tid < NPOINT) {
        const int p = tid;
        const int h = p >> 4;
        const int rem = p & 15;
        const int l = rem >> 2;
        const int pt = rem & 3;

        float a = sm_aw[p];
        float mx = -1e30f;
#pragma unroll
        for (int i = 0; i < 16; ++i) mx = fmaxf(mx, sm_aw[h * 16 + i]);
        float ssum = 0.f;
#pragma unroll
        for (int i = 0; i < 16; ++i) ssum += expf(sm_aw[h * 16 + i] - mx);
        float w = expf(a - mx) / ssum;

        const int Wl = c_lvlW[l];
        const int base = c_lvlStart[l];
        const float fW = (float)Wl;
        float offx = g_P[bq * 384 + (((h * 4 + l) * 4 + pt) * 2) + 0];
        float offy = g_P[bq * 384 + (((h * 4 + l) * 4 + pt) * 2) + 1];
        float rx = refpts[(bq * NL + l) * 2 + 0];
        float ry = refpts[(bq * NL + l) * 2 + 1];
        float x = (rx + offx / fW) * fW - 0.5f;
        float y = (ry + offy / fW) * fW - 0.5f;

        const float fx = floorf(x), fy = floorf(y);
        const int x0 = (int)fx, y0 = (int)fy;
        const float wx = x - fx, wy = y - fy;
        const float bw[4] = {(1.f - wx) * (1.f - wy), wx * (1.f - wy),
                             (1.f - wx) * wy,         wx * wy};
        const int dx[4] = {0, 1, 0, 1};
        const int dy[4] = {0, 0, 1, 1};
        float tsum = 0.f;
#pragma unroll
        for (int t = 0; t < 4; ++t) {
            int xi = x0 + dx[t], yi = y0 + dy[t];
            bool valid = (xi >= 0) && (xi < Wl) && (yi >= 0) && (yi < Wl);
            float wt = valid ? w * bw[t] : 0.f;
            int xc = min(max(xi, 0), Wl - 1);
            int yc = min(max(yi, 0), Wl - 1);
            int idx4 = (base + yc * Wl + xc) * 64;   // row index in float4 units
            sPt[h * 64 + (rem & 3 ? 0 : 0) + ((p & 15) * 4 + t)] =
                make_float2(wt, __int_as_float(idx4));
            tsum += wt;
        }
        atomicAdd(&sWsum[h], tsum);
    }
    __syncthreads();

    const int s = tid >> 6;           // slice 0..3 -> heads 2s, 2s+1
    const int cq = tid & 63;          // channel quad
    const float4* vb = (const float4*)value + (size_t)b * ((size_t)LEN_V * 64) + cq;

#pragma unroll
    for (int hh = 0; hh < 2; ++hh) {
        const int h = s * 2 + hh;
        float4 acc = make_float4(0.f, 0.f, 0.f, 0.f);
#pragma unroll 8
        for (int j = 0; j < 64; ++j) {
            float2 wi = sPt[h * 64 + j];
            if (wi.x != 0.f) {
                float4 v = vb[__float_as_int(wi.y)];
                acc.x += wi.x * v.x;
                acc.y += wi.x * v.y;
                acc.z += wi.x * v.z;
                acc.w += wi.x * v.w;
            }
        }
        *(float4*)&g_agg[(((size_t)h * NQ) + bq) * DIM + cq * 4] = acc;
    }
    if (tid < NH) g_wsum[bq * NH + tid] = sWsum[tid];
}

// ---------------------------------------------------------------------------
// Per-head projection GEMM: Y[q, h*32+n] = agg[h][q,:] @ Wv[h*32+n,:]^T + wsum[q,h]*bv
// grid (ceil(NQ/64), NH), tile 64(M) x 32(N), 4x2 micro-tile per thread.
// ---------------------------------------------------------------------------
__global__ void headproj_kernel(const float* __restrict__ Wv,
                                const float* __restrict__ bv)
{
    __shared__ float As[16][68];
    __shared__ float Bs[16][36];
    const int tid = threadIdx.x;
    const int tx = tid & 15;          // m-quad
    const int ty = tid >> 4;          // n-pair 0..15
    const int h = blockIdx.y;
    const int row0 = blockIdx.x * 64;
    const int lr = tid >> 2;
    const int kq = (tid & 3) * 4;

    const float* A = g_agg + (size_t)h * NQ * DIM;
    int arow = row0 + lr; if (arow >= NQ) arow = NQ - 1;
    const float* aptr = A + (size_t)arow * DIM + kq;
    const float* wptr = Wv + (size_t)(h * 32 + (tid >> 2 & 31)) * 256 + kq;  // only tid<128 used

    float acc[4][2];
#pragma unroll
    for (int i = 0; i < 4; ++i) { acc[i][0] = 0.f; acc[i][1] = 0.f; }

    for (int kc = 0; kc < 256; kc += 16) {
        float4 va = *(const float4*)(aptr + kc);
        float4 vw;
        if (tid < 128) vw = *(const float4*)(wptr + kc);
        As[kq + 0][lr] = va.x; As[kq + 1][lr] = va.y;
        As[kq + 2][lr] = va.z; As[kq + 3][lr] = va.w;
        if (tid < 128) {
            int r = tid >> 2;  // 0..31
            Bs[kq + 0][r] = vw.x; Bs[kq + 1][r] = vw.y;
            Bs[kq + 2][r] = vw.z; Bs[kq + 3][r] = vw.w;
        }
        __syncthreads();
#pragma unroll
        for (int k = 0; k < 16; ++k) {
            float4 a4 = ((const float4*)As[k])[tx];
            float b0 = Bs[k][ty * 2 + 0];
            float b1 = Bs[k][ty * 2 + 1];
            acc[0][0] += a4.x * b0; acc[0][1] += a4.x * b1;
            acc[1][0] += a4.y * b0; acc[1][1] += a4.y * b1;
            acc[2][0] += a4.z * b0; acc[2][1] += a4.z * b1;
            acc[3][0] += a4.w * b0; acc[3][1] += a4.w * b1;
        }
        __syncthreads();
    }

    float bv0 = bv[h * 32 + ty * 2 + 0];
    float bv1 = bv[h * 32 + ty * 2 + 1];
#pragma unroll
    for (int i = 0; i < 4; ++i) {
        int r = row0 + tx * 4 + i;
        if (r < NQ) {
            float ws = g_wsum[r * NH + h];
            float2 o = make_float2(acc[i][0] + ws * bv0, acc[i][1] + ws * bv1);
            *(float2*)(&g_Y[(size_t)r * 256 + h * 32 + ty * 2]) = o;
        }
    }
}

// ---------------------------------------------------------------------------
extern "C" void kernel_launch(void* const* d_in, const int* in_sizes, int n_in,
                              void* d_out, int out_size) {
    const float* query  = (const float*)d_in[0];
    const float* refpts = (const float*)d_in[1];
    const float* value  = (const float*)d_in[2];
    const float* Wv     = (const float*)d_in[3];
    const float* bv     = (const float*)d_in[4];
    const float* Woff   = (const float*)d_in[5];
    const float* boff   = (const float*)d_in[6];
    const float* Wattn  = (const float*)d_in[7];
    const float* battn  = (const float*)d_in[8];
    const float* Wout   = (const float*)d_in[9];
    const float* bout   = (const float*)d_in[10];
    float* out = (float*)d_out;

    float *pP = nullptr, *pY = nullptr;
    cudaGetSymbolAddress((void**)&pP, g_P);
    cudaGetSymbolAddress((void**)&pY, g_Y);

    const int MB = (NQ + 63) / 64;   // 38

    // sampling offsets (256 cols) + attention logits (128 cols) -> g_P [2400 x 384]
    gemm_kernel<<<dim3(MB, 4), 256>>>(query, 256, Woff, boff, pP, 384, 0, NQ);
    gemm_kernel<<<dim3(MB, 2), 256>>>(query, 256, Wattn, battn, pP, 384, 256, NQ);
    // fused softmax/loc prep + weighted value gather -> g_agg [h][q][c], g_wsum
    gather_kernel<<<NQ, 256>>>(value, refpts);
    // per-head value projection on aggregates -> g_Y [2400 x 256]
    headproj_kernel<<<dim3(MB, NH), 256>>>(Wv, bv);
    // output projection -> out
    gemm_kernel<<<dim3(MB, 4), 256>>>(pY, 256, Wout, bout, out, 256, 0, NQ);
}

// round 4
// speedup vs baseline: 3.4294x; 1.2110x over previous
#include <cuda_runtime.h>
#include <math.h>

#define BS 8
#define LQ 300
#define NQ (BS*LQ)        // 2400
#define DIM 256
#define NH 8
#define NL 4
#define NP 4
#define LEN_V 34000
#define NPOINT 128        // NH*NL*NP

__constant__ int c_lvlW[4]     = {160, 80, 40, 20};
__constant__ int c_lvlStart[4] = {0, 25600, 32000, 33600};

// Scratch
__device__ float g_P[NQ * 384];                    // [off(256) | attn(128)]
__device__ float g_agg[(size_t)NH * NQ * DIM];     // [h][q][c]
__device__ float g_wsum[NQ * NH];
__device__ float g_Y[NQ * DIM];

// ---------------------------------------------------------------------------
// Double-buffered register-blocked GEMM, dual weight set.
// blockIdx.y < nyW0 : C[m, y*64+n]            = A[m,:] @ W0[y*64+n,:]^T + b0
// blockIdx.y >= nyW0: C[m, nyW0*64+(y')*64+n] = A[m,:] @ W1[(y')*64+n,:]^T + b1
// tile 64(M) x 64(N), K-chunk 16, 256 threads, 4x4 micro-tile.
// ---------------------------------------------------------------------------
__global__ void gemm_dual_kernel(const float* __restrict__ A, int lda,
                                 const float* __restrict__ W0,
                                 const float* __restrict__ b0, int nyW0,
                                 const float* __restrict__ W1,
                                 const float* __restrict__ b1,
                                 float* __restrict__ C, int ldc, int M)
{
    __shared__ float As[2][16][68];
    __shared__ float Bs[2][16][68];
    const int tid = threadIdx.x;
    const int tx = tid & 15;          // m-quad
    const int ty = tid >> 4;          // n-quad
    const int row0 = blockIdx.x * 64;
    const int lr = tid >> 2;          // 0..63
    const int kq = (tid & 3) * 4;     // 0,4,8,12

    const float* W; const float* bias; int col0, colOff;
    if ((int)blockIdx.y < nyW0) {
        W = W0; bias = b0; col0 = blockIdx.y * 64; colOff = 0;
    } else {
        W = W1; bias = b1; col0 = (blockIdx.y - nyW0) * 64; colOff = nyW0 * 64;
    }

    int arow = row0 + lr; if (arow >= M) arow = M - 1;
    const float* aptr = A + (size_t)arow * lda + kq;
    const float* wptr = W + (size_t)(col0 + lr) * 256 + kq;

    float acc[4][4];
#pragma unroll
    for (int i = 0; i < 4; ++i)
#pragma unroll
        for (int j = 0; j < 4; ++j) acc[i][j] = 0.f;

    float4 va = *(const float4*)(aptr);
    float4 vw = *(const float4*)(wptr);

    int buf = 0;
    for (int kc = 0; kc < 256; kc += 16) {
        As[buf][kq + 0][lr] = va.x; As[buf][kq + 1][lr] = va.y;
        As[buf][kq + 2][lr] = va.z; As[buf][kq + 3][lr] = va.w;
        Bs[buf][kq + 0][lr] = vw.x; Bs[buf][kq + 1][lr] = vw.y;
        Bs[buf][kq + 2][lr] = vw.z; Bs[buf][kq + 3][lr] = vw.w;
        __syncthreads();
        if (kc + 16 < 256) {
            va = *(const float4*)(aptr + kc + 16);
            vw = *(const float4*)(wptr + kc + 16);
        }
#pragma unroll
        for (int k = 0; k < 16; ++k) {
            float4 a4 = ((const float4*)As[buf][k])[tx];
            float4 b4 = ((const float4*)Bs[buf][k])[ty];
            float a[4] = {a4.x, a4.y, a4.z, a4.w};
            float b[4] = {b4.x, b4.y, b4.z, b4.w};
#pragma unroll
            for (int i = 0; i < 4; ++i)
#pragma unroll
                for (int j = 0; j < 4; ++j)
                    acc[i][j] += a[i] * b[j];
        }
        buf ^= 1;
    }

    const int gc = col0 + ty * 4;
    float4 bv4 = make_float4(bias[gc], bias[gc + 1], bias[gc + 2], bias[gc + 3]);
#pragma unroll
    for (int i = 0; i < 4; ++i) {
        int r = row0 + tx * 4 + i;
        if (r < M) {
            float4 o = make_float4(acc[i][0] + bv4.x, acc[i][1] + bv4.y,
                                   acc[i][2] + bv4.z, acc[i][3] + bv4.w);
            *(float4*)(&C[(size_t)r * ldc + colOff + gc]) = o;
        }
    }
}

// ---------------------------------------------------------------------------
// Fused prep + gather. One block per query (unchanged hot path — L2-traffic floor).
// ---------------------------------------------------------------------------
__global__ void gather_kernel(const float* __restrict__ value,
                              const float* __restrict__ refpts)
{
    __shared__ float2 sPt[NH * 64];   // [h][rem*4+t] = (weight, row idx in float4 units)
    __shared__ float  sm_aw[NPOINT];
    __shared__ float  sWsum[NH];

    const int bq = blockIdx.x;
    const int b = bq / LQ;
    const int tid = threadIdx.x;

    if (tid < NH) sWsum[tid] = 0.f;
    if (tid < NPOINT) sm_aw[tid] = g_P[bq * 384 + 256 + tid];
    __syncthreads();

    if (tid < NPOINT) {
        const int p = tid;
        const int h = p >> 4;
        const int rem = p & 15;
        const int l = rem >> 2;
        const int pt = rem & 3;

        float a = sm_aw[p];
        float mx = -1e30f;
#pragma unroll
        for (int i = 0; i < 16; ++i) mx = fmaxf(mx, sm_aw[h * 16 + i]);
        float ssum = 0.f;
#pragma unroll
        for (int i = 0; i < 16; ++i) ssum += expf(sm_aw[h * 16 + i] - mx);
        float w = expf(a - mx) / ssum;

        const int Wl = c_lvlW[l];
        const int base = c_lvlStart[l];
        const float fW = (float)Wl;
        float offx = g_P[bq * 384 + (((h * 4 + l) * 4 + pt) * 2) + 0];
        float offy = g_P[bq * 384 + (((h * 4 + l) * 4 + pt) * 2) + 1];
        float rx = refpts[(bq * NL + l) * 2 + 0];
        float ry = refpts[(bq * NL + l) * 2 + 1];
        float x = (rx + offx / fW) * fW - 0.5f;
        float y = (ry + offy / fW) * fW - 0.5f;

        const float fx = floorf(x), fy = floorf(y);
        const int x0 = (int)fx, y0 = (int)fy;
        const float wx = x - fx, wy = y - fy;
        const float bw[4] = {(1.f - wx) * (1.f - wy), wx * (1.f - wy),
                             (1.f - wx) * wy,         wx * wy};
        const int dx[4] = {0, 1, 0, 1};
        const int dy[4] = {0, 0, 1, 1};
        float tsum = 0.f;
#pragma unroll
        for (int t = 0; t < 4; ++t) {
            int xi = x0 + dx[t], yi = y0 + dy[t];
            bool valid = (xi >= 0) && (xi < Wl) && (yi >= 0) && (yi < Wl);
            float wt = valid ? w * bw[t] : 0.f;
            int xc = min(max(xi, 0), Wl - 1);
            int yc = min(max(yi, 0), Wl - 1);
            int idx4 = (base + yc * Wl + xc) * 64;   // row index in float4 units
            sPt[h * 64 + rem * 4 + t] = make_float2(wt, __int_as_float(idx4));
            tsum += wt;
        }
        atomicAdd(&sWsum[h], tsum);
    }
    __syncthreads();

    const int s = tid >> 6;           // slice 0..3 -> heads 2s, 2s+1
    const int cq = tid & 63;          // channel quad
    const float4* vb = (const float4*)value + (size_t)b * ((size_t)LEN_V * 64) + cq;

#pragma unroll
    for (int hh = 0; hh < 2; ++hh) {
        const int h = s * 2 + hh;
        float4 acc = make_float4(0.f, 0.f, 0.f, 0.f);
#pragma unroll 8
        for (int j = 0; j < 64; ++j) {
            float2 wi = sPt[h * 64 + j];
            if (wi.x != 0.f) {
                float4 v = vb[__float_as_int(wi.y)];
                acc.x += wi.x * v.x;
                acc.y += wi.x * v.y;
                acc.z += wi.x * v.z;
                acc.w += wi.x * v.w;
            }
        }
        *(float4*)&g_agg[(((size_t)h * NQ) + bq) * DIM + cq * 4] = acc;
    }
    if (tid < NH) g_wsum[bq * NH + tid] = sWsum[tid];
}

// ---------------------------------------------------------------------------
// Per-head projection, 2 heads per block: tile 64(M queries) x 64(N outputs).
// grid (38, 4); output cols [hp*64, hp*64+64) span heads h0=2hp, h1=2hp+1.
// Double-buffered, single sync per K-chunk.
// ---------------------------------------------------------------------------
__global__ void headproj2_kernel(const float* __restrict__ Wv,
                                 const float* __restrict__ bv)
{
    __shared__ float As[2][16][2][68];   // [buf][k][head][row]
    __shared__ float Bs[2][16][68];
    const int tid = threadIdx.x;
    const int tx = tid & 15;             // m-quad
    const int ty = tid >> 4;             // n-quad (0..7 -> h0, 8..15 -> h1)
    const int hp = blockIdx.y;
    const int row0 = blockIdx.x * 64;
    const int lr = tid >> 2;
    const int kq = (tid & 3) * 4;

    const float* A0 = g_agg + (size_t)(2 * hp) * NQ * DIM;
    const float* A1 = g_agg + (size_t)(2 * hp + 1) * NQ * DIM;
    int arow = row0 + lr; if (arow >= NQ) arow = NQ - 1;
    const float* aptr0 = A0 + (size_t)arow * DIM + kq;
    const float* aptr1 = A1 + (size_t)arow * DIM + kq;
    const float* wptr = Wv + (size_t)(hp * 64 + lr) * 256 + kq;

    float acc[4][4];
#pragma unroll
    for (int i = 0; i < 4; ++i)
#pragma unroll
        for (int j = 0; j < 4; ++j) acc[i][j] = 0.f;

    float4 va0 = *(const float4*)(aptr0);
    float4 va1 = *(const float4*)(aptr1);
    float4 vw  = *(const float4*)(wptr);

    int buf = 0;
    for (int kc = 0; kc < 256; kc += 16) {
        As[buf][kq + 0][0][lr] = va0.x; As[buf][kq + 1][0][lr] = va0.y;
        As[buf][kq + 2][0][lr] = va0.z; As[buf][kq + 3][0][lr] = va0.w;
        As[buf][kq + 0][1][lr] = va1.x; As[buf][kq + 1][1][lr] = va1.y;
        As[buf][kq + 2][1][lr] = va1.z; As[buf][kq + 3][1][lr] = va1.w;
        Bs[buf][kq + 0][lr] = vw.x; Bs[buf][kq + 1][lr] = vw.y;
        Bs[buf][kq + 2][lr] = vw.z; Bs[buf][kq + 3][lr] = vw.w;
        __syncthreads();
        if (kc + 16 < 256) {
            va0 = *(const float4*)(aptr0 + kc + 16);
            va1 = *(const float4*)(aptr1 + kc + 16);
            vw  = *(const float4*)(wptr  + kc + 16);
        }
#pragma unroll
        for (int k = 0; k < 16; ++k) {
            float4 a4 = ((const float4*)As[buf][k][ty >> 3])[tx];
            float4 b4 = ((const float4*)Bs[buf][k])[ty];
            float a[4] = {a4.x, a4.y, a4.z, a4.w};
            float b[4] = {b4.x, b4.y, b4.z, b4.w};
#pragma unroll
            for (int i = 0; i < 4; ++i)
#pragma unroll
                for (int j = 0; j < 4; ++j)
                    acc[i][j] += a[i] * b[j];
        }
        buf ^= 1;
    }

    const int gc = hp * 64 + ty * 4;       // global output col (4-aligned)
    const int h = gc >> 5;                 // owning head
    float4 bv4 = make_float4(bv[gc], bv[gc + 1], bv[gc + 2], bv[gc + 3]);
#pragma unroll
    for (int i = 0; i < 4; ++i) {
        int r = row0 + tx * 4 + i;
        if (r < NQ) {
            float ws = g_wsum[r * NH + h];
            float4 o = make_float4(acc[i][0] + ws * bv4.x, acc[i][1] + ws * bv4.y,
                                   acc[i][2] + ws * bv4.z, acc[i][3] + ws * bv4.w);
            *(float4*)(&g_Y[(size_t)r * 256 + gc]) = o;
        }
    }
}

// ---------------------------------------------------------------------------
extern "C" void kernel_launch(void* const* d_in, const int* in_sizes, int n_in,
                              void* d_out, int out_size) {
    const float* query  = (const float*)d_in[0];
    const float* refpts = (const float*)d_in[1];
    const float* value  = (const float*)d_in[2];
    const float* Wv     = (const float*)d_in[3];
    const float* bv     = (const float*)d_in[4];
    const float* Woff   = (const float*)d_in[5];
    const float* boff   = (const float*)d_in[6];
    const float* Wattn  = (const float*)d_in[7];
    const float* battn  = (const float*)d_in[8];
    const float* Wout   = (const float*)d_in[9];
    const float* bout   = (const float*)d_in[10];
    float* out = (float*)d_out;

    float *pP = nullptr, *pY = nullptr;
    cudaGetSymbolAddress((void**)&pP, g_P);
    cudaGetSymbolAddress((void**)&pY, g_Y);

    const int MB = (NQ + 63) / 64;   // 38

    // qproj: y 0..3 -> Woff (cols 0..255), y 4..5 -> Wattn (cols 256..383)
    gemm_dual_kernel<<<dim3(MB, 6), 256>>>(query, 256, Woff, boff, 4,
                                           Wattn, battn, pP, 384, NQ);
    // fused softmax/loc prep + weighted value gather -> g_agg [h][q][c], g_wsum
    gather_kernel<<<NQ, 256>>>(value, refpts);
    // per-head value projection on aggregates -> g_Y [2400 x 256]
    headproj2_kernel<<<dim3(MB, 4), 256>>>(Wv, bv);
    // output projection -> out
    gemm_dual_kernel<<<dim3(MB, 4), 256>>>(pY, 256, Wout, bout, 4,
                                           (const float*)nullptr,
                                           (const float*)nullptr, out, 256, NQ);
}

// round 5
// speedup vs baseline: 3.4865x; 1.0167x over previous
#include <cuda_runtime.h>
#include <math.h>

#define BS 8
#define LQ 300
#define NQ (BS*LQ)        // 2400
#define DIM 256
#define NH 8
#define NL 4
#define NP 4
#define LEN_V 34000
#define NPOINT 128        // NH*NL*NP

__constant__ int c_lvlW[4]     = {160, 80, 40, 20};
__constant__ int c_lvlStart[4] = {0, 25600, 32000, 33600};

// Scratch
__device__ float g_P[NQ * 384];                    // [off(256) | attn(128)]
__device__ float g_agg[(size_t)NH * NQ * DIM];     // [h][q][c]
__device__ float g_wsum[NQ * NH];
__device__ float g_Y[NQ * DIM];

// ---------------------------------------------------------------------------
// Double-buffered GEMM, dual weight set. Tile 32(M) x 64(N), 128 threads,
// 4x4 micro-tile. Grid.x = M/32 (=75) -> 2-3 blocks/SM, latency overlapped.
// blockIdx.y < nyW0 : cols [y*64, y*64+64) from W0 ; else from W1 at colOff.
// ---------------------------------------------------------------------------
__global__ void gemm_dual_kernel(const float* __restrict__ A, int lda,
                                 const float* __restrict__ W0,
                                 const float* __restrict__ b0, int nyW0,
                                 const float* __restrict__ W1,
                                 const float* __restrict__ b1,
                                 float* __restrict__ C, int ldc, int M)
{
    __shared__ float As[2][16][36];
    __shared__ float Bs[2][16][68];
    const int tid = threadIdx.x;      // 0..127
    const int tx = tid & 7;           // m-quad
    const int ty = tid >> 3;          // n-quad 0..15
    const int row0 = blockIdx.x * 32;
    const int ar = tid >> 2;          // 0..31  (A load row)
    const int akq = (tid & 3) * 4;
    const int br = tid >> 1;          // 0..63  (B load row)
    const int bkq = (tid & 1) * 8;

    const float* W; const float* bias; int col0, colOff;
    if ((int)blockIdx.y < nyW0) {
        W = W0; bias = b0; col0 = blockIdx.y * 64; colOff = 0;
    } else {
        W = W1; bias = b1; col0 = (blockIdx.y - nyW0) * 64; colOff = nyW0 * 64;
    }

    const float* aptr = A + (size_t)(row0 + ar) * lda + akq;
    const float* wptr = W + (size_t)(col0 + br) * 256 + bkq;

    float acc[4][4];
#pragma unroll
    for (int i = 0; i < 4; ++i)
#pragma unroll
        for (int j = 0; j < 4; ++j) acc[i][j] = 0.f;

    float4 va  = *(const float4*)(aptr);
    float4 vw0 = *(const float4*)(wptr);
    float4 vw1 = *(const float4*)(wptr + 4);

    int buf = 0;
    for (int kc = 0; kc < 256; kc += 16) {
        As[buf][akq + 0][ar] = va.x;  As[buf][akq + 1][ar] = va.y;
        As[buf][akq + 2][ar] = va.z;  As[buf][akq + 3][ar] = va.w;
        Bs[buf][bkq + 0][br] = vw0.x; Bs[buf][bkq + 1][br] = vw0.y;
        Bs[buf][bkq + 2][br] = vw0.z; Bs[buf][bkq + 3][br] = vw0.w;
        Bs[buf][bkq + 4][br] = vw1.x; Bs[buf][bkq + 5][br] = vw1.y;
        Bs[buf][bkq + 6][br] = vw1.z; Bs[buf][bkq + 7][br] = vw1.w;
        __syncthreads();
        if (kc + 16 < 256) {
            va  = *(const float4*)(aptr + kc + 16);
            vw0 = *(const float4*)(wptr + kc + 16);
            vw1 = *(const float4*)(wptr + kc + 20);
        }
#pragma unroll
        for (int k = 0; k < 16; ++k) {
            float4 a4 = ((const float4*)As[buf][k])[tx];
            float4 b4 = ((const float4*)Bs[buf][k])[ty];
            float a[4] = {a4.x, a4.y, a4.z, a4.w};
            float b[4] = {b4.x, b4.y, b4.z, b4.w};
#pragma unroll
            for (int i = 0; i < 4; ++i)
#pragma unroll
                for (int j = 0; j < 4; ++j)
                    acc[i][j] += a[i] * b[j];
        }
        buf ^= 1;
    }

    const int gc = col0 + ty * 4;
    float4 bv4 = make_float4(bias[gc], bias[gc + 1], bias[gc + 2], bias[gc + 3]);
#pragma unroll
    for (int i = 0; i < 4; ++i) {
        int r = row0 + tx * 4 + i;
        if (r < M) {
            float4 o = make_float4(acc[i][0] + bv4.x, acc[i][1] + bv4.y,
                                   acc[i][2] + bv4.z, acc[i][3] + bv4.w);
            *(float4*)(&C[(size_t)r * ldc + colOff + gc]) = o;
        }
    }
}

// ---------------------------------------------------------------------------
// Fused prep + gather. One block per query. Branch-free tap loop, taps packed
// 2-per-float4 in smem, 4 independent LDG.128 per unrolled step.
// ---------------------------------------------------------------------------
__global__ void gather_kernel(const float* __restrict__ value,
                              const float* __restrict__ refpts)
{
    __shared__ float4 sPt4[NH * 32];  // [h][j]: taps 2j,2j+1 = (w0,idx0,w1,idx1)
    __shared__ float  sm_aw[NPOINT];
    __shared__ float  sWsum[NH];

    const int bq = blockIdx.x;
    const int b = bq / LQ;
    const int tid = threadIdx.x;

    if (tid < NH) sWsum[tid] = 0.f;
    if (tid < NPOINT) sm_aw[tid] = g_P[bq * 384 + 256 + tid];
    __syncthreads();

    if (tid < NPOINT) {
        const int p = tid;
        const int h = p >> 4;
        const int rem = p & 15;
        const int l = rem >> 2;
        const int pt = rem & 3;

        float a = sm_aw[p];
        float mx = -1e30f;
#pragma unroll
        for (int i = 0; i < 16; ++i) mx = fmaxf(mx, sm_aw[h * 16 + i]);
        float ssum = 0.f;
#pragma unroll
        for (int i = 0; i < 16; ++i) ssum += expf(sm_aw[h * 16 + i] - mx);
        float w = expf(a - mx) / ssum;

        const int Wl = c_lvlW[l];
        const int base = c_lvlStart[l];
        const float fW = (float)Wl;
        float offx = g_P[bq * 384 + (((h * 4 + l) * 4 + pt) * 2) + 0];
        float offy = g_P[bq * 384 + (((h * 4 + l) * 4 + pt) * 2) + 1];
        float rx = refpts[(bq * NL + l) * 2 + 0];
        float ry = refpts[(bq * NL + l) * 2 + 1];
        float x = (rx + offx / fW) * fW - 0.5f;
        float y = (ry + offy / fW) * fW - 0.5f;

        const float fx = floorf(x), fy = floorf(y);
        const int x0 = (int)fx, y0 = (int)fy;
        const float wx = x - fx, wy = y - fy;
        const float bw[4] = {(1.f - wx) * (1.f - wy), wx * (1.f - wy),
                             (1.f - wx) * wy,         wx * wy};
        const int dx[4] = {0, 1, 0, 1};
        const int dy[4] = {0, 0, 1, 1};
        float wt[4]; int idx4[4];
        float tsum = 0.f;
#pragma unroll
        for (int t = 0; t < 4; ++t) {
            int xi = x0 + dx[t], yi = y0 + dy[t];
            bool valid = (xi >= 0) && (xi < Wl) && (yi >= 0) && (yi < Wl);
            wt[t] = valid ? w * bw[t] : 0.f;
            int xc = min(max(xi, 0), Wl - 1);
            int yc = min(max(yi, 0), Wl - 1);
            idx4[t] = (base + yc * Wl + xc) * 64;   // row index in float4 units
            tsum += wt[t];
        }
        sPt4[h * 32 + rem * 2 + 0] =
            make_float4(wt[0], __int_as_float(idx4[0]), wt[1], __int_as_float(idx4[1]));
        sPt4[h * 32 + rem * 2 + 1] =
            make_float4(wt[2], __int_as_float(idx4[2]), wt[3], __int_as_float(idx4[3]));
        atomicAdd(&sWsum[h], tsum);
    }
    __syncthreads();

    const int s = tid >> 6;           // slice 0..3 -> heads 2s, 2s+1
    const int cq = tid & 63;          // channel quad
    const float4* vb = (const float4*)value + (size_t)b * ((size_t)LEN_V * 64) + cq;

#pragma unroll
    for (int hh = 0; hh < 2; ++hh) {
        const int h = s * 2 + hh;
        float accx = 0.f, accy = 0.f, accz = 0.f, accw = 0.f;
#pragma unroll 4
        for (int j = 0; j < 32; j += 2) {
            float4 p0 = sPt4[h * 32 + j];
            float4 p1 = sPt4[h * 32 + j + 1];
            float4 v0 = vb[__float_as_int(p0.y)];
            float4 v1 = vb[__float_as_int(p0.w)];
            float4 v2 = vb[__float_as_int(p1.y)];
            float4 v3 = vb[__float_as_int(p1.w)];
            accx += p0.x * v0.x + p0.z * v1.x + p1.x * v2.x + p1.z * v3.x;
            accy += p0.x * v0.y + p0.z * v1.y + p1.x * v2.y + p1.z * v3.y;
            accz += p0.x * v0.z + p0.z * v1.z + p1.x * v2.z + p1.z * v3.z;
            accw += p0.x * v0.w + p0.z * v1.w + p1.x * v2.w + p1.z * v3.w;
        }
        *(float4*)&g_agg[(((size_t)h * NQ) + bq) * DIM + cq * 4] =
            make_float4(accx, accy, accz, accw);
    }
    if (tid < NH) g_wsum[bq * NH + tid] = sWsum[tid];
}

// ---------------------------------------------------------------------------
// Per-head projection: tile 32(M) x 64(N), 128 threads, grid (75, 4).
// Col block y spans heads 2y (cols 0..31 of block) and 2y+1 (cols 32..63).
// ---------------------------------------------------------------------------
__global__ void headproj_kernel(const float* __restrict__ Wv,
                                const float* __restrict__ bv)
{
    __shared__ float As[2][16][2][36];   // [buf][k][head][row]
    __shared__ float Bs[2][16][68];
    const int tid = threadIdx.x;
    const int tx = tid & 7;
    const int ty = tid >> 3;             // 0..7 -> head0 cols, 8..15 -> head1
    const int hp = blockIdx.y;
    const int row0 = blockIdx.x * 32;
    const int ar = tid >> 2;             // 0..31
    const int akq = (tid & 3) * 4;
    const int br = tid >> 1;             // 0..63
    const int bkq = (tid & 1) * 8;

    const float* aptr0 = g_agg + (size_t)(2 * hp) * NQ * DIM + (size_t)(row0 + ar) * DIM + akq;
    const float* aptr1 = g_agg + (size_t)(2 * hp + 1) * NQ * DIM + (size_t)(row0 + ar) * DIM + akq;
    const float* wptr  = Wv + (size_t)(hp * 64 + br) * 256 + bkq;

    float acc[4][4];
#pragma unroll
    for (int i = 0; i < 4; ++i)
#pragma unroll
        for (int j = 0; j < 4; ++j) acc[i][j] = 0.f;

    float4 va0 = *(const float4*)(aptr0);
    float4 va1 = *(const float4*)(aptr1);
    float4 vw0 = *(const float4*)(wptr);
    float4 vw1 = *(const float4*)(wptr + 4);

    int buf = 0;
    for (int kc = 0; kc < 256; kc += 16) {
        As[buf][akq + 0][0][ar] = va0.x; As[buf][akq + 1][0][ar] = va0.y;
        As[buf][akq + 2][0][ar] = va0.z; As[buf][akq + 3][0][ar] = va0.w;
        As[buf][akq + 0][1][ar] = va1.x; As[buf][akq + 1][1][ar] = va1.y;
        As[buf][akq + 2][1][ar] = va1.z; As[buf][akq + 3][1][ar] = va1.w;
        Bs[buf][bkq + 0][br] = vw0.x; Bs[buf][bkq + 1][br] = vw0.y;
        Bs[buf][bkq + 2][br] = vw0.z; Bs[buf][bkq + 3][br] = vw0.w;
        Bs[buf][bkq + 4][br] = vw1.x; Bs[buf][bkq + 5][br] = vw1.y;
        Bs[buf][bkq + 6][br] = vw1.z; Bs[buf][bkq + 7][br] = vw1.w;
        __syncthreads();
        if (kc + 16 < 256) {
            va0 = *(const float4*)(aptr0 + kc + 16);
            va1 = *(const float4*)(aptr1 + kc + 16);
            vw0 = *(const float4*)(wptr  + kc + 16);
            vw1 = *(const float4*)(wptr  + kc + 20);
        }
#pragma unroll
        for (int k = 0; k < 16; ++k) {
            float4 a4 = ((const float4*)As[buf][k][ty >> 3])[tx];
            float4 b4 = ((const float4*)Bs[buf][k])[ty];
            float a[4] = {a4.x, a4.y, a4.z, a4.w};
            float b[4] = {b4.x, b4.y, b4.z, b4.w};
#pragma unroll
            for (int i = 0; i < 4; ++i)
#pragma unroll
                for (int j = 0; j < 4; ++j)
                    acc[i][j] += a[i] * b[j];
        }
        buf ^= 1;
    }

    const int gc = hp * 64 + ty * 4;
    const int h = gc >> 5;
    float4 bv4 = make_float4(bv[gc], bv[gc + 1], bv[gc + 2], bv[gc + 3]);
#pragma unroll
    for (int i = 0; i < 4; ++i) {
        int r = row0 + tx * 4 + i;
        if (r < NQ) {
            float ws = g_wsum[r * NH + h];
            float4 o = make_float4(acc[i][0] + ws * bv4.x, acc[i][1] + ws * bv4.y,
                                   acc[i][2] + ws * bv4.z, acc[i][3] + ws * bv4.w);
            *(float4*)(&g_Y[(size_t)r * 256 + gc]) = o;
        }
    }
}

// ---------------------------------------------------------------------------
extern "C" void kernel_launch(void* const* d_in, const int* in_sizes, int n_in,
                              void* d_out, int out_size) {
    const float* query  = (const float*)d_in[0];
    const float* refpts = (const float*)d_in[1];
    const float* value  = (const float*)d_in[2];
    const float* Wv     = (const float*)d_in[3];
    const float* bv     = (const float*)d_in[4];
    const float* Woff   = (const float*)d_in[5];
    const float* boff   = (const float*)d_in[6];
    const float* Wattn  = (const float*)d_in[7];
    const float* battn  = (const float*)d_in[8];
    const float* Wout   = (const float*)d_in[9];
    const float* bout   = (const float*)d_in[10];
    float* out = (float*)d_out;

    float *pP = nullptr, *pY = nullptr;
    cudaGetSymbolAddress((void**)&pP, g_P);
    cudaGetSymbolAddress((void**)&pY, g_Y);

    const int MB = NQ / 32;   // 75

    // qproj: y 0..3 -> Woff (cols 0..255), y 4..5 -> Wattn (cols 256..383)
    gemm_dual_kernel<<<dim3(MB, 6), 128>>>(query, 256, Woff, boff, 4,
                                           Wattn, battn, pP, 384, NQ);
    // fused softmax/loc prep + weighted value gather -> g_agg [h][q][c], g_wsum
    gather_kernel<<<NQ, 256>>>(value, refpts);
    // per-head value projection on aggregates -> g_Y [2400 x 256]
    headproj_kernel<<<dim3(MB, 4), 128>>>(Wv, bv);
    // output projection -> out
    gemm_dual_kernel<<<dim3(MB, 4), 128>>>(pY, 256, Wout, bout, 4,
                                           (const float*)nullptr,
                                           (const float*)nullptr, out, 256, NQ);
}